// round 4
// baseline (speedup 1.0000x reference)
#include <cuda_runtime.h>
#include <cstdint>

#define TILE   128
#define NTH    256
#define MAX_E  800000

// ---- shared memory layout (byte offsets) ----
#define SM_ROWS 0          // int[128]
#define SM_COLS 512        // int[128]
#define SM_EIDX 1024       // int[128]
#define SM_B1   1536       // float[256]
#define SM_B2   2560       // float[128]
#define SM_A    3072       // 128 x 192 tf32, stride 196 words (784B): 100352 B
#define SM_B0   103424     // weight buffer 0: 50176 B
#define SM_BB1  153600     // weight buffer 1: 50176 B
#define SMEM_TOTAL 203776

__device__ int g_cnt[2];
__device__ int g_list[2 * MAX_E];
// pre-converted tf32 weight images in exact smem (ldmatrix) layout
__device__ uint32_t gW1t[2 * 4 * 64 * 196];    // [flavor][chunk][nl<64][196w]
__device__ uint32_t gW2t[2 * 4 * 128 * 68];    // [flavor][chunk][nl<128][68w]

// ---------------- helpers ----------------
static __device__ __forceinline__ uint32_t smem_u32(const void* p) {
    uint32_t a;
    asm("{ .reg .u64 t; cvta.to.shared.u64 t, %1; cvt.u32.u64 %0, t; }"
        : "=r"(a) : "l"(p));
    return a;
}
static __device__ __forceinline__ uint32_t f2tf(float f) {
    uint32_t r; asm("cvt.rna.tf32.f32 %0, %1;" : "=r"(r) : "f"(f)); return r;
}
static __device__ __forceinline__ void sts128(uint32_t a, uint32_t r0, uint32_t r1,
                                              uint32_t r2, uint32_t r3) {
    asm volatile("st.shared.v4.b32 [%0], {%1,%2,%3,%4};"
                 :: "r"(a), "r"(r0), "r"(r1), "r"(r2), "r"(r3) : "memory");
}
static __device__ __forceinline__ void ldsm_x4(uint32_t r[4], uint32_t addr) {
    asm volatile("ldmatrix.sync.aligned.m8n8.x4.shared.b16 {%0,%1,%2,%3}, [%4];"
                 : "=r"(r[0]), "=r"(r[1]), "=r"(r[2]), "=r"(r[3]) : "r"(addr));
}
static __device__ __forceinline__ void mma_tf32(float d[4], const uint32_t a[4],
                                                const uint32_t b[2]) {
    asm("mma.sync.aligned.m16n8k8.row.col.f32.tf32.tf32.f32 "
        "{%0,%1,%2,%3}, {%4,%5,%6,%7}, {%8,%9}, {%0,%1,%2,%3};"
        : "+f"(d[0]), "+f"(d[1]), "+f"(d[2]), "+f"(d[3])
        : "r"(a[0]), "r"(a[1]), "r"(a[2]), "r"(a[3]), "r"(b[0]), "r"(b[1]));
}
static __device__ __forceinline__ void red_add(float* p, float v) {
    asm volatile("red.global.add.f32 [%0], %1;" :: "l"(p), "f"(v) : "memory");
}
static __device__ __forceinline__ void cpa16(uint32_t d, const uint32_t* s) {
    asm volatile("cp.async.ca.shared.global [%0], [%1], 16;"
                 :: "r"(d), "l"(s) : "memory");
}
#define CP_COMMIT() asm volatile("cp.async.commit_group;" ::: "memory")
#define CP_WAIT(n)  asm volatile("cp.async.wait_group %0;" :: "n"(n) : "memory")

// ---------------- prep kernels ----------------
__global__ void reset_kernel() { g_cnt[0] = 0; g_cnt[1] = 0; }

__global__ void prep_w1(const float* __restrict__ W1o, const float* __restrict__ W1i) {
    int idx = blockIdx.x * 256 + threadIdx.x;      // 2*4*64*192
    if (idx >= 2 * 4 * 64 * 192) return;
    int k = idx % 192; int t = idx / 192;
    int nl = t & 63; t >>= 6;
    int c = t & 3; int f = t >> 2;
    const float* W = f ? W1i : W1o;
    gW1t[(size_t)((f * 4 + c) * 64 + nl) * 196 + k] = f2tf(W[k * 256 + c * 64 + nl]);
}
__global__ void prep_w2(const float* __restrict__ W2o, const float* __restrict__ W2i) {
    int idx = blockIdx.x * 256 + threadIdx.x;      // 2*4*128*64
    if (idx >= 2 * 4 * 128 * 64) return;
    int kk = idx % 64; int t = idx / 64;
    int nl = t & 127; t >>= 7;
    int c = t & 3; int f = t >> 2;
    const float* W = f ? W2i : W2o;
    gW2t[(size_t)((f * 4 + c) * 128 + nl) * 68 + kk] = f2tf(W[(c * 64 + kk) * 128 + nl]);
}

__global__ void partition_kernel(const int* __restrict__ ei, int E) {
    int e = blockIdx.x * blockDim.x + threadIdx.x;
    bool valid = e < E;
    int r = 0, c = 0;
    if (valid) { r = ei[e]; c = ei[E + e]; }
    int lane = threadIdx.x & 31;
    bool po = valid && (r < c);   // flow_out
    bool pi = valid && (r > c);   // flow_in
    unsigned mo = __ballot_sync(0xffffffffu, po);
    unsigned mi = __ballot_sync(0xffffffffu, pi);
    int lo = __ffs(mo) - 1, li = __ffs(mi) - 1;
    int bo = 0, bi = 0;
    if (mo && lane == lo) bo = atomicAdd(&g_cnt[0], __popc(mo));
    if (mi && lane == li) bi = atomicAdd(&g_cnt[1], __popc(mi));
    if (mo) bo = __shfl_sync(0xffffffffu, bo, lo);
    if (mi) bi = __shfl_sync(0xffffffffu, bi, li);
    unsigned lt = (1u << lane) - 1u;
    if (po) g_list[bo + __popc(mo & lt)] = e;
    if (pi) g_list[MAX_E + bi + __popc(mi & lt)] = e;
}

// ---------------- chunk copy (cp.async, contiguous) ----------------
static __device__ __forceinline__ void cp_w1_chunk(int flavor, int c, uint32_t dst,
                                                   int tid) {
    const uint32_t* src = gW1t + (size_t)(flavor * 4 + c) * (64 * 196);
    #pragma unroll
    for (int i = 0; i < 13; i++) {
        int s = tid + i * NTH;
        if (s < 3136) cpa16(dst + s * 16, src + s * 4);
    }
}
static __device__ __forceinline__ void cp_w2_chunk(int flavor, int c, uint32_t dst,
                                                   int tid) {
    const uint32_t* src = gW2t + (size_t)(flavor * 4 + c) * (128 * 68);
    #pragma unroll
    for (int i = 0; i < 9; i++) {
        int s = tid + i * NTH;
        if (s < 2176) cpa16(dst + s * 16, src + s * 4);
    }
}

// ---------------- main kernel ----------------
__global__ __launch_bounds__(NTH, 1)
void mlp_kernel(const float* __restrict__ x, const int* __restrict__ ei,
                const float* __restrict__ ea,
                const float* __restrict__ b1o, const float* __restrict__ b2o,
                const float* __restrict__ b1i, const float* __restrict__ b2i,
                int E, float* __restrict__ out) {
    int flavor = blockIdx.y;
    int cnt = g_cnt[flavor];
    int base = blockIdx.x * TILE;
    if (base >= cnt) return;
    int nvalid = min(TILE, cnt - base);
    const int* list = g_list + flavor * MAX_E;
    int colOff = flavor ? 0 : 128;   // in -> [0,128), out -> [128,256)
    const float* b1 = flavor ? b1i : b1o;
    const float* b2 = flavor ? b2i : b2o;

    extern __shared__ __align__(16) char smem[];
    uint32_t sb = smem_u32(smem);
    uint32_t sbA = sb + SM_A;
    uint32_t wbuf[2] = { sb + SM_B0, sb + SM_BB1 };
    int tid = threadIdx.x, wid = tid >> 5, lane = tid & 31;

    // prefetch W1 chunk 0 immediately
    cp_w1_chunk(flavor, 0, wbuf[0], tid);
    CP_COMMIT();

    // header: edge ids / endpoints / biases
    if (tid < TILE) {
        int e = list[base + min(tid, nvalid - 1)];
        ((int*)(smem + SM_EIDX))[tid] = e;
        ((int*)(smem + SM_ROWS))[tid] = ei[e];
        ((int*)(smem + SM_COLS))[tid] = ei[E + e];
    }
    ((float*)(smem + SM_B1))[tid] = b1[tid];
    if (tid < 128) ((float*)(smem + SM_B2))[tid] = b2[tid];
    __syncthreads();

    // ---- gather A = [x[col] | edge_attr] as tf32, row-major stride 196 words ----
    {
        int r = tid & 127, h = tid >> 7;
        int cnode = ((const int*)(smem + SM_COLS))[r];
        int eidx  = ((const int*)(smem + SM_EIDX))[r];
        const float4* xr = (const float4*)(x + (size_t)cnode * 128);
        const float4* er = (const float4*)(ea + (size_t)eidx * 64);
        #pragma unroll
        for (int q = 0; q < 24; q++) {
            int kq = h + 2 * q;                 // 0..47 (k = 4*kq)
            float4 v = (kq < 32) ? xr[kq] : er[kq - 32];
            sts128(sbA + r * 784 + kq * 16,
                   f2tf(v.x), f2tf(v.y), f2tf(v.z), f2tf(v.w));
        }
    }

    // per-lane ldmatrix bases
    uint32_t aB  = sbA + (wid * 16 + (lane & 15)) * 784 + (lane >> 4) * 16;
    // B x4 base: lanes 16-31 address the next n-tile (rows +8)
    uint32_t bo1 = (uint32_t)((lane & 7) + ((lane >> 4) << 3)) * 784
                 + (uint32_t)(((lane >> 3) & 1) << 4);
    uint32_t bo2 = (uint32_t)((lane & 7) + ((lane >> 4) << 3)) * 272
                 + (uint32_t)(((lane >> 3) & 1) << 4);

    // ---- GEMM1: h[128x256] = A[128x192] @ W1, 4 n-chunks, double-buffered ----
    float acc1[32][4];
    #pragma unroll
    for (int j = 0; j < 32; j++)
        #pragma unroll
        for (int p = 0; p < 4; p++) acc1[j][p] = 0.0f;

    #pragma unroll
    for (int c = 0; c < 4; c++) {
        if (c < 3) { cp_w1_chunk(flavor, c + 1, wbuf[(c + 1) & 1], tid); CP_COMMIT(); }
        else       { cp_w2_chunk(flavor, 0, wbuf[0], tid); CP_COMMIT(); }
        CP_WAIT(1);
        __syncthreads();
        uint32_t bufB = wbuf[c & 1] + bo1;
        for (int s = 0; s < 24; s++) {
            uint32_t af[4]; ldsm_x4(af, aB + s * 32);
            #pragma unroll
            for (int nt2 = 0; nt2 < 4; nt2++) {
                uint32_t bf4[4];
                ldsm_x4(bf4, bufB + nt2 * (2 * 6272) + s * 32);
                mma_tf32(acc1[8 * c + 2 * nt2],     af, bf4);
                mma_tf32(acc1[8 * c + 2 * nt2 + 1], af, bf4 + 2);
            }
        }
        __syncthreads();
    }

    // ---- bias + ReLU + tf32-convert, h stays in acc1 registers ----
    {
        const float* b1s = (const float*)(smem + SM_B1);
        int t2 = 2 * (lane & 3);
        #pragma unroll
        for (int j = 0; j < 32; j++) {
            #pragma unroll
            for (int p = 0; p < 4; p++) {
                float v = acc1[j][p] + b1s[8 * j + t2 + (p & 1)];
                acc1[j][p] = __uint_as_float(f2tf(fmaxf(v, 0.0f)));
            }
        }
    }

    // ---- GEMM2: out2[128x128] = h @ W2, 4 k-chunks, double-buffered ----
    float acc2[16][4];
    #pragma unroll
    for (int j = 0; j < 16; j++)
        #pragma unroll
        for (int p = 0; p < 4; p++) acc2[j][p] = 0.0f;

    int sl0 = (lane >> 2) * 4 + ((lane & 3) >> 1);
    int sl1 = sl0 + 2;
    bool oddl = (lane & 1);

    #pragma unroll
    for (int cc = 0; cc < 4; cc++) {
        if (cc < 3) { cp_w2_chunk(flavor, cc + 1, wbuf[(cc + 1) & 1], tid); CP_COMMIT(); }
        if (cc < 3) CP_WAIT(1); else CP_WAIT(0);
        __syncthreads();
        uint32_t bufB = wbuf[cc & 1] + bo2;
        #pragma unroll
        for (int s2 = 0; s2 < 8; s2++) {
            int j = cc * 8 + s2;               // h n-tile == GEMM2 k-block
            float v00 = __shfl_sync(0xffffffffu, acc1[j][0], sl0);
            float v01 = __shfl_sync(0xffffffffu, acc1[j][1], sl0);
            float v20 = __shfl_sync(0xffffffffu, acc1[j][2], sl0);
            float v21 = __shfl_sync(0xffffffffu, acc1[j][3], sl0);
            float w00 = __shfl_sync(0xffffffffu, acc1[j][0], sl1);
            float w01 = __shfl_sync(0xffffffffu, acc1[j][1], sl1);
            float w20 = __shfl_sync(0xffffffffu, acc1[j][2], sl1);
            float w21 = __shfl_sync(0xffffffffu, acc1[j][3], sl1);
            uint32_t af[4];
            af[0] = __float_as_uint(oddl ? v01 : v00);
            af[1] = __float_as_uint(oddl ? v21 : v20);
            af[2] = __float_as_uint(oddl ? w01 : w00);
            af[3] = __float_as_uint(oddl ? w21 : w20);
            #pragma unroll
            for (int nt2 = 0; nt2 < 8; nt2++) {
                uint32_t bf4[4];
                ldsm_x4(bf4, bufB + nt2 * (2 * 2176) + s2 * 32);
                mma_tf32(acc2[2 * nt2],     af, bf4);
                mma_tf32(acc2[2 * nt2 + 1], af, bf4 + 2);
            }
        }
        __syncthreads();
    }

    // ---- epilogue: scatter-add valid rows ----
    {
        const float* b2s = (const float*)(smem + SM_B2);
        const int* rows = (const int*)(smem + SM_ROWS);
        int m1 = wid * 16 + (lane >> 2);
        int m2 = m1 + 8;
        bool ok1 = m1 < nvalid, ok2 = m2 < nvalid;
        float* o1 = ok1 ? (out + (size_t)rows[m1] * 256 + colOff) : out;
        float* o2 = ok2 ? (out + (size_t)rows[m2] * 256 + colOff) : out;
        int t2 = 2 * (lane & 3);
        #pragma unroll
        for (int nt = 0; nt < 16; nt++) {
            int n0 = 8 * nt + t2;
            if (ok1) {
                red_add(o1 + n0,     acc2[nt][0] + b2s[n0]);
                red_add(o1 + n0 + 1, acc2[nt][1] + b2s[n0 + 1]);
            }
            if (ok2) {
                red_add(o2 + n0,     acc2[nt][2] + b2s[n0]);
                red_add(o2 + n0 + 1, acc2[nt][3] + b2s[n0 + 1]);
            }
        }
    }
}

// ---------------- host launch ----------------
extern "C" void kernel_launch(void* const* d_in, const int* in_sizes, int n_in,
                              void* d_out, int out_size) {
    const float* x   = (const float*)d_in[0];
    const int*   ei  = (const int*)  d_in[1];
    const float* ea  = (const float*)d_in[2];
    const float* W1o = (const float*)d_in[3];
    const float* b1o = (const float*)d_in[4];
    const float* W2o = (const float*)d_in[5];
    const float* b2o = (const float*)d_in[6];
    const float* W1i = (const float*)d_in[7];
    const float* b1i = (const float*)d_in[8];
    const float* W2i = (const float*)d_in[9];
    const float* b2i = (const float*)d_in[10];
    float* out = (float*)d_out;
    int E = in_sizes[1] / 2;

    static bool attr_set = false;
    if (!attr_set) {
        cudaFuncSetAttribute(mlp_kernel, cudaFuncAttributeMaxDynamicSharedMemorySize,
                             SMEM_TOTAL);
        attr_set = true;
    }

    cudaMemsetAsync(d_out, 0, (size_t)out_size * sizeof(float));
    reset_kernel<<<1, 1>>>();
    prep_w1<<<(2 * 4 * 64 * 192 + 255) / 256, 256>>>(W1o, W1i);
    prep_w2<<<(2 * 4 * 128 * 64 + 255) / 256, 256>>>(W2o, W2i);
    partition_kernel<<<(E + 255) / 256, 256>>>(ei, E);

    dim3 grid((E + TILE - 1) / TILE, 2);
    mlp_kernel<<<grid, NTH, SMEM_TOTAL>>>(x, ei, ea, b1o, b2o, b1i, b2i, E, out);
}

// round 5
// speedup vs baseline: 1.2072x; 1.2072x over previous
#include <cuda_runtime.h>
#include <cstdint>

#define TILE   128
#define NTH    256
#define MAX_E  800000
#define NCAP   50048

// ---- mlp kernel smem layout (bytes) ----
#define SM_ROWS 0          // int[128]
#define SM_COLS 512        // int[128]
#define SM_EIDX 1024       // int[128]
#define SM_B2   1536       // float[128]
#define SM_A    2048       // 128 rows x 272 B (64 tf32 + pad): 34816
#define SM_W1E  36864      // 256 rows x 272 B: 69632
#define SM_W2A  106496     // 128 rows x 272 B: 34816
#define SM_W2B  141312     // 128 rows x 272 B: 34816
#define SMEM_MLP 176128

// ---- pcomp kernel smem layout ----
#define PC_B1   0          // float[256]
#define PC_A    1024       // 128 rows x 528 B: 67584
#define PC_W    69632      // 256 rows x 528 B: 135168  (1024+67584 aligned up)
#define SMEM_PC 204800

__device__ int g_cnt[2];
__device__ int g_list[2 * MAX_E];
// tf32 weight images in smem (ldmatrix) layout
__device__ uint32_t gW1et[2 * 256 * 68];    // [f][n<256][k<64 +pad]  (ea part of W1)
__device__ uint32_t gW1xt[2 * 256 * 132];   // [f][n<256][k<128 +pad] (x part of W1)
__device__ uint32_t gW2t[2 * 4 * 128 * 68]; // [f][chunk][n<128][kk<64 +pad]
// P[f][node][q<4][j<32][b<2] = x[node]@W1x_f + b1_f  (fragment-permuted rows)
__device__ float g_P[2 * (size_t)NCAP * 256];

// ---------------- helpers ----------------
static __device__ __forceinline__ uint32_t smem_u32(const void* p) {
    uint32_t a;
    asm("{ .reg .u64 t; cvta.to.shared.u64 t, %1; cvt.u32.u64 %0, t; }"
        : "=r"(a) : "l"(p));
    return a;
}
static __device__ __forceinline__ uint32_t f2tf(float f) {
    uint32_t r; asm("cvt.rna.tf32.f32 %0, %1;" : "=r"(r) : "f"(f)); return r;
}
static __device__ __forceinline__ void sts128(uint32_t a, uint32_t r0, uint32_t r1,
                                              uint32_t r2, uint32_t r3) {
    asm volatile("st.shared.v4.b32 [%0], {%1,%2,%3,%4};"
                 :: "r"(a), "r"(r0), "r"(r1), "r"(r2), "r"(r3) : "memory");
}
static __device__ __forceinline__ void ldsm_x4(uint32_t r[4], uint32_t addr) {
    asm volatile("ldmatrix.sync.aligned.m8n8.x4.shared.b16 {%0,%1,%2,%3}, [%4];"
                 : "=r"(r[0]), "=r"(r[1]), "=r"(r[2]), "=r"(r[3]) : "r"(addr));
}
static __device__ __forceinline__ void mma_tf32(float d[4], const uint32_t a[4],
                                                const uint32_t b[2]) {
    asm("mma.sync.aligned.m16n8k8.row.col.f32.tf32.tf32.f32 "
        "{%0,%1,%2,%3}, {%4,%5,%6,%7}, {%8,%9}, {%0,%1,%2,%3};"
        : "+f"(d[0]), "+f"(d[1]), "+f"(d[2]), "+f"(d[3])
        : "r"(a[0]), "r"(a[1]), "r"(a[2]), "r"(a[3]), "r"(b[0]), "r"(b[1]));
}
static __device__ __forceinline__ void red_add(float* p, float v) {
    asm volatile("red.global.add.f32 [%0], %1;" :: "l"(p), "f"(v) : "memory");
}
static __device__ __forceinline__ void cpa16(uint32_t d, const uint32_t* s) {
    asm volatile("cp.async.ca.shared.global [%0], [%1], 16;"
                 :: "r"(d), "l"(s) : "memory");
}
#define CP_COMMIT() asm volatile("cp.async.commit_group;" ::: "memory")
#define CP_WAIT(n)  asm volatile("cp.async.wait_group %0;" :: "n"(n) : "memory")

// ---------------- setup kernels ----------------
__global__ void reset_kernel() { g_cnt[0] = 0; g_cnt[1] = 0; }

// one fused prep: builds gW1et (32768), gW2t (65536), gW1xt (65536)
__global__ void prep_kernel(const float* __restrict__ W1o, const float* __restrict__ W1i,
                            const float* __restrict__ W2o, const float* __restrict__ W2i) {
    int idx = blockIdx.x * 256 + threadIdx.x;
    if (idx < 32768) {                         // W1e: [f][nl<256][k<64]
        int k = idx & 63; int t = idx >> 6;
        int nl = t & 255; int f = t >> 8;
        const float* W = f ? W1i : W1o;
        gW1et[(size_t)(f * 256 + nl) * 68 + k] = f2tf(W[(128 + k) * 256 + nl]);
    } else if (idx < 98304) {                  // W2: [f][c<4][nl<128][kk<64]
        int i = idx - 32768;
        int kk = i & 63; int t = i >> 6;
        int nl = t & 127; t >>= 7;
        int c = t & 3; int f = t >> 2;
        const float* W = f ? W2i : W2o;
        gW2t[(size_t)((f * 4 + c) * 128 + nl) * 68 + kk] = f2tf(W[(c * 64 + kk) * 128 + nl]);
    } else if (idx < 163840) {                 // W1x: [f][nl<256][k<128]
        int i = idx - 98304;
        int k = i & 127; int t = i >> 7;
        int nl = t & 255; int f = t >> 8;
        const float* W = f ? W1i : W1o;
        gW1xt[(size_t)(f * 256 + nl) * 132 + k] = f2tf(W[k * 256 + nl]);
    }
}

__global__ void partition_kernel(const int* __restrict__ ei, int E) {
    int e = blockIdx.x * blockDim.x + threadIdx.x;
    bool valid = e < E;
    int r = 0, c = 0;
    if (valid) { r = ei[e]; c = ei[E + e]; }
    int lane = threadIdx.x & 31;
    bool po = valid && (r < c);
    bool pi = valid && (r > c);
    unsigned mo = __ballot_sync(0xffffffffu, po);
    unsigned mi = __ballot_sync(0xffffffffu, pi);
    int lo = __ffs(mo) - 1, li = __ffs(mi) - 1;
    int bo = 0, bi = 0;
    if (mo && lane == lo) bo = atomicAdd(&g_cnt[0], __popc(mo));
    if (mi && lane == li) bi = atomicAdd(&g_cnt[1], __popc(mi));
    if (mo) bo = __shfl_sync(0xffffffffu, bo, lo);
    if (mi) bi = __shfl_sync(0xffffffffu, bi, li);
    unsigned lt = (1u << lane) - 1u;
    if (po) g_list[bo + __popc(mo & lt)] = e;
    if (pi) g_list[MAX_E + bi + __popc(mi & lt)] = e;
}

// ---------------- P precompute: P = x @ W1x + b1 (per flavor) ----------------
__global__ __launch_bounds__(NTH, 1)
void pcomp_kernel(const float* __restrict__ x,
                  const float* __restrict__ b1o, const float* __restrict__ b1i,
                  int N) {
    int f = blockIdx.y;
    int base = blockIdx.x * 128;
    if (base >= N) return;
    const float* b1 = f ? b1i : b1o;

    extern __shared__ __align__(16) char smem[];
    uint32_t sb = smem_u32(smem);
    uint32_t sbA = sb + PC_A, sbW = sb + PC_W;
    int tid = threadIdx.x, wid = tid >> 5, lane = tid & 31;

    // stream W1x image (tf32, ldmatrix layout) via cp.async: 8448 x 16B
    {
        const uint32_t* src = gW1xt + (size_t)f * 256 * 132;
        #pragma unroll
        for (int i = 0; i < 33; i++) {
            int s = tid + i * NTH;
            cpa16(sbW + s * 16, src + s * 4);
        }
        CP_COMMIT();
    }
    ((float*)(smem + PC_B1))[tid] = b1[tid];

    // gather x rows -> tf32, stride 528 B
    {
        int r = tid & 127, h = tid >> 7;
        int node = min(base + r, N - 1);
        const float4* xr = (const float4*)(x + (size_t)node * 128);
        #pragma unroll
        for (int q = 0; q < 16; q++) {
            int kq = h + 2 * q;                 // 0..31
            float4 v = xr[kq];
            sts128(sbA + r * 528 + kq * 16,
                   f2tf(v.x), f2tf(v.y), f2tf(v.z), f2tf(v.w));
        }
    }
    CP_WAIT(0);
    __syncthreads();

    uint32_t aB = sbA + (wid * 16 + (lane & 15)) * 528 + (lane >> 4) * 16;
    uint32_t bB = sbW + (uint32_t)((lane & 7) + ((lane >> 4) << 3)) * 528
                + (uint32_t)(((lane >> 3) & 1) << 4);

    float acc[32][4];
    #pragma unroll
    for (int j = 0; j < 32; j++)
        #pragma unroll
        for (int p = 0; p < 4; p++) acc[j][p] = 0.0f;

    for (int s = 0; s < 16; s++) {
        uint32_t af[4]; ldsm_x4(af, aB + s * 32);
        #pragma unroll
        for (int nt2 = 0; nt2 < 16; nt2++) {
            uint32_t bf4[4];
            ldsm_x4(bf4, bB + nt2 * 8448 + s * 32);
            mma_tf32(acc[2 * nt2],     af, bf4);
            mma_tf32(acc[2 * nt2 + 1], af, bf4 + 2);
        }
    }

    // epilogue: + b1, write fragment-permuted P rows
    {
        const float* b1s = (const float*)(smem + PC_B1);
        int q = lane & 3, t2 = 2 * q;
        int m1 = wid * 16 + (lane >> 2), m2 = m1 + 8;
        int n1 = base + m1, n2 = base + m2;
        float* p1 = g_P + ((size_t)f * NCAP + n1) * 256 + q * 64;
        float* p2 = g_P + ((size_t)f * NCAP + n2) * 256 + q * 64;
        #pragma unroll
        for (int j = 0; j < 32; j += 2) {
            if (n1 < N) {
                float4 v = { acc[j][0]     + b1s[8 * j + t2],
                             acc[j][1]     + b1s[8 * j + t2 + 1],
                             acc[j + 1][0] + b1s[8 * (j + 1) + t2],
                             acc[j + 1][1] + b1s[8 * (j + 1) + t2 + 1] };
                *(float4*)(p1 + j * 2) = v;
            }
            if (n2 < N) {
                float4 v = { acc[j][2]     + b1s[8 * j + t2],
                             acc[j][3]     + b1s[8 * j + t2 + 1],
                             acc[j + 1][2] + b1s[8 * (j + 1) + t2],
                             acc[j + 1][3] + b1s[8 * (j + 1) + t2 + 1] };
                *(float4*)(p2 + j * 2) = v;
            }
        }
    }
}

// ---------------- W2 chunk copy ----------------
static __device__ __forceinline__ void cp_w2_chunk(int f, int c, uint32_t dst, int tid) {
    const uint32_t* src = gW2t + (size_t)(f * 4 + c) * (128 * 68);
    #pragma unroll
    for (int i = 0; i < 9; i++) {
        int s = tid + i * NTH;
        if (s < 2176) cpa16(dst + s * 16, src + s * 4);
    }
}

// ---------------- main edge-MLP kernel ----------------
__global__ __launch_bounds__(NTH, 1)
void mlp_kernel(const int* __restrict__ ei, const float* __restrict__ ea,
                const float* __restrict__ b2o, const float* __restrict__ b2i,
                int E, float* __restrict__ out) {
    int f = blockIdx.y;
    int cnt = g_cnt[f];
    int base = blockIdx.x * TILE;
    if (base >= cnt) return;
    int nvalid = min(TILE, cnt - base);
    const int* list = g_list + f * MAX_E;
    int colOff = f ? 0 : 128;
    const float* b2 = f ? b2i : b2o;

    extern __shared__ __align__(16) char smem[];
    uint32_t sb = smem_u32(smem);
    uint32_t sbA = sb + SM_A;
    uint32_t wbuf[2] = { sb + SM_W2A, sb + SM_W2B };
    int tid = threadIdx.x, wid = tid >> 5, lane = tid & 31;

    // stream W1e (group 0) and W2 chunk 0 (group 1)
    {
        const uint32_t* src = gW1et + (size_t)f * 256 * 68;
        #pragma unroll
        for (int i = 0; i < 17; i++) {
            int s = tid + i * NTH;
            cpa16(sb + SM_W1E + s * 16, src + s * 4);
        }
        CP_COMMIT();
    }
    cp_w2_chunk(f, 0, wbuf[0], tid);
    CP_COMMIT();

    // headers
    if (tid < TILE) {
        int e = list[base + min(tid, nvalid - 1)];
        ((int*)(smem + SM_EIDX))[tid] = e;
        ((int*)(smem + SM_ROWS))[tid] = ei[e];
        ((int*)(smem + SM_COLS))[tid] = ei[E + e];
    }
    if (tid < 128) ((float*)(smem + SM_B2))[tid] = b2[tid];
    __syncthreads();

    // ---- acc1 init from gathered P rows (fragment-permuted) ----
    float acc1[32][4];
    int q = lane & 3;
    int m1 = wid * 16 + (lane >> 2), m2 = m1 + 8;
    {
        int node1 = ((const int*)(smem + SM_COLS))[m1];
        int node2 = ((const int*)(smem + SM_COLS))[m2];
        const float4* p1 = (const float4*)(g_P + ((size_t)f * NCAP + node1) * 256 + q * 64);
        const float4* p2 = (const float4*)(g_P + ((size_t)f * NCAP + node2) * 256 + q * 64);
        #pragma unroll
        for (int i4 = 0; i4 < 16; i4++) {
            int j = 2 * i4;
            float4 v = p1[i4];
            acc1[j][0] = v.x; acc1[j][1] = v.y;
            acc1[j + 1][0] = v.z; acc1[j + 1][1] = v.w;
            float4 w = p2[i4];
            acc1[j][2] = w.x; acc1[j][3] = w.y;
            acc1[j + 1][2] = w.z; acc1[j + 1][3] = w.w;
        }
    }

    // ---- gather A = edge_attr as tf32, stride 272 B ----
    {
        int r = tid & 127, h = tid >> 7;
        int eidx = ((const int*)(smem + SM_EIDX))[r];
        const float4* er = (const float4*)(ea + (size_t)eidx * 64);
        #pragma unroll
        for (int qq = 0; qq < 8; qq++) {
            int kq = h + 2 * qq;                // 0..15
            float4 v = er[kq];
            sts128(sbA + r * 272 + kq * 16,
                   f2tf(v.x), f2tf(v.y), f2tf(v.z), f2tf(v.w));
        }
    }
    CP_WAIT(1);                                 // W1e resident (W2c0 may lag)
    __syncthreads();

    uint32_t aB = sbA + (wid * 16 + (lane & 15)) * 272 + (lane >> 4) * 16;
    uint32_t bo = (uint32_t)((lane & 7) + ((lane >> 4) << 3)) * 272
                + (uint32_t)(((lane >> 3) & 1) << 4);

    // ---- GEMM1: acc1 += A_ea[128x64] @ W1e ----
    {
        uint32_t bW = sb + SM_W1E + bo;
        for (int s = 0; s < 8; s++) {
            uint32_t af[4]; ldsm_x4(af, aB + s * 32);
            #pragma unroll
            for (int nt2 = 0; nt2 < 16; nt2++) {
                uint32_t bf4[4];
                ldsm_x4(bf4, bW + nt2 * 4352 + s * 32);
                mma_tf32(acc1[2 * nt2],     af, bf4);
                mma_tf32(acc1[2 * nt2 + 1], af, bf4 + 2);
            }
        }
    }

    // ---- ReLU + tf32-convert in registers ----
    #pragma unroll
    for (int j = 0; j < 32; j++)
        #pragma unroll
        for (int p = 0; p < 4; p++)
            acc1[j][p] = __uint_as_float(f2tf(fmaxf(acc1[j][p], 0.0f)));

    // ---- GEMM2: out2[128x128] = h @ W2, 4 k-chunks, double-buffered ----
    float acc2[16][4];
    #pragma unroll
    for (int j = 0; j < 16; j++)
        #pragma unroll
        for (int p = 0; p < 4; p++) acc2[j][p] = 0.0f;

    int sl0 = (lane >> 2) * 4 + ((lane & 3) >> 1);
    int sl1 = sl0 + 2;
    bool oddl = (lane & 1);

    #pragma unroll
    for (int cc = 0; cc < 4; cc++) {
        if (cc < 3) { cp_w2_chunk(f, cc + 1, wbuf[(cc + 1) & 1], tid); CP_COMMIT(); }
        if (cc < 3) CP_WAIT(1); else CP_WAIT(0);
        __syncthreads();
        uint32_t bufB = wbuf[cc & 1] + bo;
        #pragma unroll
        for (int s2 = 0; s2 < 8; s2++) {
            int j = cc * 8 + s2;
            float v00 = __shfl_sync(0xffffffffu, acc1[j][0], sl0);
            float v01 = __shfl_sync(0xffffffffu, acc1[j][1], sl0);
            float v20 = __shfl_sync(0xffffffffu, acc1[j][2], sl0);
            float v21 = __shfl_sync(0xffffffffu, acc1[j][3], sl0);
            float w00 = __shfl_sync(0xffffffffu, acc1[j][0], sl1);
            float w01 = __shfl_sync(0xffffffffu, acc1[j][1], sl1);
            float w20 = __shfl_sync(0xffffffffu, acc1[j][2], sl1);
            float w21 = __shfl_sync(0xffffffffu, acc1[j][3], sl1);
            uint32_t af[4];
            af[0] = __float_as_uint(oddl ? v01 : v00);
            af[1] = __float_as_uint(oddl ? v21 : v20);
            af[2] = __float_as_uint(oddl ? w01 : w00);
            af[3] = __float_as_uint(oddl ? w21 : w20);
            #pragma unroll
            for (int nt2 = 0; nt2 < 8; nt2++) {
                uint32_t bf4[4];
                ldsm_x4(bf4, bufB + nt2 * 4352 + s2 * 32);
                mma_tf32(acc2[2 * nt2],     af, bf4);
                mma_tf32(acc2[2 * nt2 + 1], af, bf4 + 2);
            }
        }
        __syncthreads();
    }

    // ---- epilogue: + b2, scatter-add valid rows ----
    {
        const float* b2s = (const float*)(smem + SM_B2);
        const int* rows = (const int*)(smem + SM_ROWS);
        bool ok1 = m1 < nvalid, ok2 = m2 < nvalid;
        float* o1 = ok1 ? (out + (size_t)rows[m1] * 256 + colOff) : out;
        float* o2 = ok2 ? (out + (size_t)rows[m2] * 256 + colOff) : out;
        int t2 = 2 * q;
        #pragma unroll
        for (int nt = 0; nt < 16; nt++) {
            int n0 = 8 * nt + t2;
            if (ok1) {
                red_add(o1 + n0,     acc2[nt][0] + b2s[n0]);
                red_add(o1 + n0 + 1, acc2[nt][1] + b2s[n0 + 1]);
            }
            if (ok2) {
                red_add(o2 + n0,     acc2[nt][2] + b2s[n0]);
                red_add(o2 + n0 + 1, acc2[nt][3] + b2s[n0 + 1]);
            }
        }
    }
}

// ---------------- host launch ----------------
extern "C" void kernel_launch(void* const* d_in, const int* in_sizes, int n_in,
                              void* d_out, int out_size) {
    const float* x   = (const float*)d_in[0];
    const int*   ei  = (const int*)  d_in[1];
    const float* ea  = (const float*)d_in[2];
    const float* W1o = (const float*)d_in[3];
    const float* b1o = (const float*)d_in[4];
    const float* W2o = (const float*)d_in[5];
    const float* b2o = (const float*)d_in[6];
    const float* W1i = (const float*)d_in[7];
    const float* b1i = (const float*)d_in[8];
    const float* W2i = (const float*)d_in[9];
    const float* b2i = (const float*)d_in[10];
    float* out = (float*)d_out;
    int E = in_sizes[1] / 2;
    int N = in_sizes[0] / 128;
    if (N > NCAP) N = NCAP;

    static bool attr_set = false;
    if (!attr_set) {
        cudaFuncSetAttribute(mlp_kernel, cudaFuncAttributeMaxDynamicSharedMemorySize,
                             SMEM_MLP);
        cudaFuncSetAttribute(pcomp_kernel, cudaFuncAttributeMaxDynamicSharedMemorySize,
                             SMEM_PC);
        attr_set = true;
    }

    cudaMemsetAsync(d_out, 0, (size_t)out_size * sizeof(float));
    reset_kernel<<<1, 1>>>();
    prep_kernel<<<640, 256>>>(W1o, W1i, W2o, W2i);
    partition_kernel<<<(E + 255) / 256, 256>>>(ei, E);
    pcomp_kernel<<<dim3((N + 127) / 128, 2), NTH, SMEM_PC>>>(x, b1o, b1i, N);

    dim3 grid((E + TILE - 1) / TILE, 2);
    mlp_kernel<<<grid, NTH, SMEM_MLP>>>(ei, ea, b2o, b2i, E, out);
}

// round 7
// speedup vs baseline: 1.6614x; 1.3762x over previous
#include <cuda_runtime.h>
#include <cstdint>

#define TILE   128
#define NTH    256
#define MAX_E  800000
#define NCAP   50048

// ---- mlp kernel smem layout (bytes) ----
#define SM_ROWS 0          // int[128]
#define SM_COLS 512        // int[128]
#define SM_EIDX 1024       // int[128]
#define SM_B2   1536       // float[128]
#define SM_A    2048       // 128 rows x 144 B (64 f16 + pad): 18432
#define SM_W1E  20480      // 256 rows x 144 B: 36864
#define SM_W2   57344      // 128 rows x 528 B: 67584
#define SMEM_MLP 124928

// ---- pcomp kernel smem layout ----
#define PC_B1   0          // float[256]
#define PC_A    1024       // 128 rows x 272 B: 34816
#define PC_W    35840      // 256 rows x 272 B: 69632
#define SMEM_PC 105472

__device__ int g_cnt[2];
__device__ int g_list[2 * MAX_E];
// packed fp16 weight images in smem (ldmatrix) layout, incl. row pads
__device__ uint32_t gW1eh[2 * 256 * 36];    // [f][n<256][kpair<32 +pad]
__device__ uint32_t gW1xh[2 * 256 * 68];    // [f][n<256][kpair<64 +pad]
__device__ uint32_t gW2h [2 * 128 * 132];   // [f][n<128][kpair<128 +pad]
// P[f][node][q<4][j2<16][4] = x[node]@W1x_f + b1_f (fragment-permuted rows)
__device__ float g_P[2 * (size_t)NCAP * 256];

// ---------------- helpers ----------------
static __device__ __forceinline__ uint32_t smem_u32(const void* p) {
    uint32_t a;
    asm("{ .reg .u64 t; cvta.to.shared.u64 t, %1; cvt.u32.u64 %0, t; }"
        : "=r"(a) : "l"(p));
    return a;
}
static __device__ __forceinline__ uint32_t pack_h2(float lo, float hi) {
    uint32_t r;
    asm("cvt.rn.f16x2.f32 %0, %1, %2;" : "=r"(r) : "f"(hi), "f"(lo));
    return r;
}
static __device__ __forceinline__ void sts128(uint32_t a, uint32_t r0, uint32_t r1,
                                              uint32_t r2, uint32_t r3) {
    asm volatile("st.shared.v4.b32 [%0], {%1,%2,%3,%4};"
                 :: "r"(a), "r"(r0), "r"(r1), "r"(r2), "r"(r3) : "memory");
}
static __device__ __forceinline__ void ldsm_x4(uint32_t r[4], uint32_t addr) {
    asm volatile("ldmatrix.sync.aligned.m8n8.x4.shared.b16 {%0,%1,%2,%3}, [%4];"
                 : "=r"(r[0]), "=r"(r[1]), "=r"(r[2]), "=r"(r[3]) : "r"(addr));
}
static __device__ __forceinline__ void mma_f16(float d[4], const uint32_t a[4],
                                               const uint32_t b[2]) {
    asm("mma.sync.aligned.m16n8k16.row.col.f32.f16.f16.f32 "
        "{%0,%1,%2,%3}, {%4,%5,%6,%7}, {%8,%9}, {%0,%1,%2,%3};"
        : "+f"(d[0]), "+f"(d[1]), "+f"(d[2]), "+f"(d[3])
        : "r"(a[0]), "r"(a[1]), "r"(a[2]), "r"(a[3]), "r"(b[0]), "r"(b[1]));
}
static __device__ __forceinline__ void red_add(float* p, float v) {
    asm volatile("red.global.add.f32 [%0], %1;" :: "l"(p), "f"(v) : "memory");
}
static __device__ __forceinline__ void cpa16(uint32_t d, const uint32_t* s) {
    asm volatile("cp.async.ca.shared.global [%0], [%1], 16;"
                 :: "r"(d), "l"(s) : "memory");
}
#define CP_COMMIT() asm volatile("cp.async.commit_group;" ::: "memory")
#define CP_WAIT(n)  asm volatile("cp.async.wait_group %0;" :: "n"(n) : "memory")

// ---------------- setup kernels ----------------
__global__ void reset_kernel() { g_cnt[0] = 0; g_cnt[1] = 0; }

// builds packed fp16 images: W1e (16384 pairs), W1x (32768), W2 (32768)
__global__ void prep_kernel(const float* __restrict__ W1o, const float* __restrict__ W1i,
                            const float* __restrict__ W2o, const float* __restrict__ W2i) {
    int idx = blockIdx.x * 256 + threadIdx.x;
    if (idx < 16384) {                          // W1e: [f][nl<256][p<32]
        int p = idx & 31; int t = idx >> 5;
        int nl = t & 255; int f = t >> 8;
        const float* W = f ? W1i : W1o;
        gW1eh[(f * 256 + nl) * 36 + p] =
            pack_h2(W[(128 + 2 * p) * 256 + nl], W[(129 + 2 * p) * 256 + nl]);
    } else if (idx < 49152) {                   // W1x: [f][nl<256][p<64]
        int i = idx - 16384;
        int p = i & 63; int t = i >> 6;
        int nl = t & 255; int f = t >> 8;
        const float* W = f ? W1i : W1o;
        gW1xh[(f * 256 + nl) * 68 + p] =
            pack_h2(W[(2 * p) * 256 + nl], W[(2 * p + 1) * 256 + nl]);
    } else if (idx < 81920) {                   // W2: [f][nl<128][p<128]
        int i = idx - 49152;
        int p = i & 127; int t = i >> 7;
        int nl = t & 127; int f = t >> 7;       // FIXED (was t>>7>>7 == 0)
        const float* W = f ? W2i : W2o;
        gW2h[(f * 128 + nl) * 132 + p] =
            pack_h2(W[(2 * p) * 128 + nl], W[(2 * p + 1) * 128 + nl]);
    }
}

__global__ void partition_kernel(const int* __restrict__ ei, int E) {
    int e = blockIdx.x * blockDim.x + threadIdx.x;
    bool valid = e < E;
    int r = 0, c = 0;
    if (valid) { r = ei[e]; c = ei[E + e]; }
    int lane = threadIdx.x & 31;
    bool po = valid && (r < c);
    bool pi = valid && (r > c);
    unsigned mo = __ballot_sync(0xffffffffu, po);
    unsigned mi = __ballot_sync(0xffffffffu, pi);
    int lo = __ffs(mo) - 1, li = __ffs(mi) - 1;
    int bo = 0, bi = 0;
    if (mo && lane == lo) bo = atomicAdd(&g_cnt[0], __popc(mo));
    if (mi && lane == li) bi = atomicAdd(&g_cnt[1], __popc(mi));
    if (mo) bo = __shfl_sync(0xffffffffu, bo, lo);
    if (mi) bi = __shfl_sync(0xffffffffu, bi, li);
    unsigned lt = (1u << lane) - 1u;
    if (po) g_list[bo + __popc(mo & lt)] = e;
    if (pi) g_list[MAX_E + bi + __popc(mi & lt)] = e;
}

// ---------------- P precompute: P = x @ W1x + b1 (per flavor) ----------------
__global__ __launch_bounds__(NTH, 1)
void pcomp_kernel(const float* __restrict__ x,
                  const float* __restrict__ b1o, const float* __restrict__ b1i,
                  int N) {
    int f = blockIdx.y;
    int base = blockIdx.x * 128;
    if (base >= N) return;
    const float* b1 = f ? b1i : b1o;

    extern __shared__ __align__(16) char smem[];
    uint32_t sb = smem_u32(smem);
    uint32_t sbA = sb + PC_A, sbW = sb + PC_W;
    int tid = threadIdx.x, wid = tid >> 5, lane = tid & 31;

    // stream W1x image via cp.async: 4352 x 16B
    {
        const uint32_t* src = gW1xh + (size_t)f * 256 * 68;
        #pragma unroll
        for (int i = 0; i < 17; i++) {
            int s = tid + i * NTH;
            cpa16(sbW + s * 16, src + s * 4);
        }
        CP_COMMIT();
    }
    ((float*)(smem + PC_B1))[tid] = b1[tid];

    // gather x rows -> f16, stride 272 B
    {
        int r = tid & 127, h = tid >> 7;
        int node = min(base + r, N - 1);
        const float4* xr = (const float4*)(x + (size_t)node * 128);
        #pragma unroll
        for (int q = 0; q < 8; q++) {
            float4 a = xr[h * 16 + 2 * q], b = xr[h * 16 + 2 * q + 1];
            sts128(sbA + r * 272 + h * 128 + q * 16,
                   pack_h2(a.x, a.y), pack_h2(a.z, a.w),
                   pack_h2(b.x, b.y), pack_h2(b.z, b.w));
        }
    }
    CP_WAIT(0);
    __syncthreads();

    uint32_t aB = sbA + (wid * 16 + (lane & 15)) * 272 + (lane >> 4) * 16;
    uint32_t bB = sbW + (uint32_t)((lane & 7) + ((lane >> 4) << 3)) * 272
                + (uint32_t)(((lane >> 3) & 1) << 4);

    float acc[32][4];
    #pragma unroll
    for (int j = 0; j < 32; j++)
        #pragma unroll
        for (int p = 0; p < 4; p++) acc[j][p] = 0.0f;

    for (int s = 0; s < 8; s++) {
        uint32_t af[4]; ldsm_x4(af, aB + s * 32);
        #pragma unroll
        for (int nt2 = 0; nt2 < 16; nt2++) {
            uint32_t bf4[4];
            ldsm_x4(bf4, bB + nt2 * 4352 + s * 32);
            mma_f16(acc[2 * nt2],     af, bf4);
            mma_f16(acc[2 * nt2 + 1], af, bf4 + 2);
        }
    }

    // epilogue: + b1, write fragment-permuted P rows
    {
        const float* b1s = (const float*)(smem + PC_B1);
        int q = lane & 3, t2 = 2 * q;
        int m1 = wid * 16 + (lane >> 2), m2 = m1 + 8;
        int n1 = base + m1, n2 = base + m2;
        float* p1 = g_P + ((size_t)f * NCAP + n1) * 256 + q * 64;
        float* p2 = g_P + ((size_t)f * NCAP + n2) * 256 + q * 64;
        #pragma unroll
        for (int j = 0; j < 32; j += 2) {
            if (n1 < N) {
                float4 v = { acc[j][0]     + b1s[8 * j + t2],
                             acc[j][1]     + b1s[8 * j + t2 + 1],
                             acc[j + 1][0] + b1s[8 * (j + 1) + t2],
                             acc[j + 1][1] + b1s[8 * (j + 1) + t2 + 1] };
                *(float4*)(p1 + j * 2) = v;
            }
            if (n2 < N) {
                float4 v = { acc[j][2]     + b1s[8 * j + t2],
                             acc[j][3]     + b1s[8 * j + t2 + 1],
                             acc[j + 1][2] + b1s[8 * (j + 1) + t2],
                             acc[j + 1][3] + b1s[8 * (j + 1) + t2 + 1] };
                *(float4*)(p2 + j * 2) = v;
            }
        }
    }
}

// ---------------- main edge-MLP kernel ----------------
__global__ __launch_bounds__(NTH, 1)
void mlp_kernel(const int* __restrict__ ei, const float* __restrict__ ea,
                const float* __restrict__ b2o, const float* __restrict__ b2i,
                int E, float* __restrict__ out) {
    int f = blockIdx.y;
    int cnt = g_cnt[f];
    int base = blockIdx.x * TILE;
    if (base >= cnt) return;
    int nvalid = min(TILE, cnt - base);
    const int* list = g_list + f * MAX_E;
    int colOff = f ? 0 : 128;
    const float* b2 = f ? b2i : b2o;

    extern __shared__ __align__(16) char smem[];
    uint32_t sb = smem_u32(smem);
    uint32_t sbA = sb + SM_A;
    int tid = threadIdx.x, wid = tid >> 5, lane = tid & 31;

    // stream W1e (group 0): 2304 x 16B;  W2 (group 1): 4224 x 16B
    {
        const uint32_t* src = gW1eh + (size_t)f * 256 * 36;
        #pragma unroll
        for (int i = 0; i < 9; i++) {
            int s = tid + i * NTH;
            cpa16(sb + SM_W1E + s * 16, src + s * 4);
        }
        CP_COMMIT();
    }
    {
        const uint32_t* src = gW2h + (size_t)f * 128 * 132;
        #pragma unroll
        for (int i = 0; i < 17; i++) {
            int s = tid + i * NTH;
            if (s < 4224) cpa16(sb + SM_W2 + s * 16, src + s * 4);
        }
        CP_COMMIT();
    }

    // headers
    if (tid < TILE) {
        int e = list[base + min(tid, nvalid - 1)];
        ((int*)(smem + SM_EIDX))[tid] = e;
        ((int*)(smem + SM_ROWS))[tid] = ei[e];
        ((int*)(smem + SM_COLS))[tid] = ei[E + e];
    }
    if (tid < 128) ((float*)(smem + SM_B2))[tid] = b2[tid];
    __syncthreads();

    // ---- acc1 init from gathered P rows (fragment-permuted) ----
    float acc1[32][4];
    int q = lane & 3;
    int m1 = wid * 16 + (lane >> 2), m2 = m1 + 8;
    {
        int node1 = ((const int*)(smem + SM_COLS))[m1];
        int node2 = ((const int*)(smem + SM_COLS))[m2];
        const float4* p1 = (const float4*)(g_P + ((size_t)f * NCAP + node1) * 256 + q * 64);
        const float4* p2 = (const float4*)(g_P + ((size_t)f * NCAP + node2) * 256 + q * 64);
        #pragma unroll
        for (int i4 = 0; i4 < 16; i4++) {
            int j = 2 * i4;
            float4 v = p1[i4];
            acc1[j][0] = v.x; acc1[j][1] = v.y;
            acc1[j + 1][0] = v.z; acc1[j + 1][1] = v.w;
            float4 w = p2[i4];
            acc1[j][2] = w.x; acc1[j][3] = w.y;
            acc1[j + 1][2] = w.z; acc1[j + 1][3] = w.w;
        }
    }

    // ---- gather A = edge_attr as f16, stride 144 B ----
    {
        int r = tid & 127, h = tid >> 7;
        int eidx = ((const int*)(smem + SM_EIDX))[r];
        const float4* er = (const float4*)(ea + (size_t)eidx * 64);
        #pragma unroll
        for (int qq = 0; qq < 4; qq++) {
            float4 a = er[h * 8 + 2 * qq], b = er[h * 8 + 2 * qq + 1];
            sts128(sbA + r * 144 + h * 64 + qq * 16,
                   pack_h2(a.x, a.y), pack_h2(a.z, a.w),
                   pack_h2(b.x, b.y), pack_h2(b.z, b.w));
        }
    }
    CP_WAIT(1);          // W1e resident (W2 may lag)
    __syncthreads();

    uint32_t aB = sbA + (wid * 16 + (lane & 15)) * 144 + (lane >> 4) * 16;
    uint32_t bo144 = (uint32_t)((lane & 7) + ((lane >> 4) << 3)) * 144
                   + (uint32_t)(((lane >> 3) & 1) << 4);
    uint32_t bo528 = (uint32_t)((lane & 7) + ((lane >> 4) << 3)) * 528
                   + (uint32_t)(((lane >> 3) & 1) << 4);

    // ---- GEMM1: acc1 += A_ea[128x64] @ W1e  (4 k16-steps) ----
    {
        uint32_t bW = sb + SM_W1E + bo144;
        #pragma unroll
        for (int s = 0; s < 4; s++) {
            uint32_t af[4]; ldsm_x4(af, aB + s * 32);
            #pragma unroll
            for (int nt2 = 0; nt2 < 16; nt2++) {
                uint32_t bf4[4];
                ldsm_x4(bf4, bW + nt2 * 2304 + s * 32);
                mma_f16(acc1[2 * nt2],     af, bf4);
                mma_f16(acc1[2 * nt2 + 1], af, bf4 + 2);
            }
        }
    }
    CP_WAIT(0);          // W2 resident
    __syncthreads();

    // ---- GEMM2: out2[128x128] = relu(h) @ W2  (16 k16-steps, A from regs) ----
    float acc2[16][4];
    #pragma unroll
    for (int j = 0; j < 16; j++)
        #pragma unroll
        for (int p = 0; p < 4; p++) acc2[j][p] = 0.0f;

    {
        uint32_t bW = sb + SM_W2 + bo528;
        #pragma unroll
        for (int s2 = 0; s2 < 16; s2++) {
            int j = 2 * s2;
            uint32_t af[4];
            af[0] = pack_h2(fmaxf(acc1[j][0], 0.f),     fmaxf(acc1[j][1], 0.f));
            af[1] = pack_h2(fmaxf(acc1[j][2], 0.f),     fmaxf(acc1[j][3], 0.f));
            af[2] = pack_h2(fmaxf(acc1[j + 1][0], 0.f), fmaxf(acc1[j + 1][1], 0.f));
            af[3] = pack_h2(fmaxf(acc1[j + 1][2], 0.f), fmaxf(acc1[j + 1][3], 0.f));
            #pragma unroll
            for (int nt2 = 0; nt2 < 8; nt2++) {
                uint32_t bf4[4];
                ldsm_x4(bf4, bW + nt2 * 8448 + s2 * 32);
                mma_f16(acc2[2 * nt2],     af, bf4);
                mma_f16(acc2[2 * nt2 + 1], af, bf4 + 2);
            }
        }
    }

    // ---- epilogue: + b2, scatter-add valid rows ----
    {
        const float* b2s = (const float*)(smem + SM_B2);
        const int* rows = (const int*)(smem + SM_ROWS);
        bool ok1 = m1 < nvalid, ok2 = m2 < nvalid;
        float* o1 = ok1 ? (out + (size_t)rows[m1] * 256 + colOff) : out;
        float* o2 = ok2 ? (out + (size_t)rows[m2] * 256 + colOff) : out;
        int t2 = 2 * q;
        #pragma unroll
        for (int nt = 0; nt < 16; nt++) {
            int n0 = 8 * nt + t2;
            if (ok1) {
                red_add(o1 + n0,     acc2[nt][0] + b2s[n0]);
                red_add(o1 + n0 + 1, acc2[nt][1] + b2s[n0 + 1]);
            }
            if (ok2) {
                red_add(o2 + n0,     acc2[nt][2] + b2s[n0]);
                red_add(o2 + n0 + 1, acc2[nt][3] + b2s[n0 + 1]);
            }
        }
    }
}

// ---------------- host launch ----------------
extern "C" void kernel_launch(void* const* d_in, const int* in_sizes, int n_in,
                              void* d_out, int out_size) {
    const float* x   = (const float*)d_in[0];
    const int*   ei  = (const int*)  d_in[1];
    const float* ea  = (const float*)d_in[2];
    const float* W1o = (const float*)d_in[3];
    const float* b1o = (const float*)d_in[4];
    const float* W2o = (const float*)d_in[5];
    const float* b2o = (const float*)d_in[6];
    const float* W1i = (const float*)d_in[7];
    const float* b1i = (const float*)d_in[8];
    const float* W2i = (const float*)d_in[9];
    const float* b2i = (const float*)d_in[10];
    float* out = (float*)d_out;
    int E = in_sizes[1] / 2;
    int N = in_sizes[0] / 128;
    if (N > NCAP) N = NCAP;

    static bool attr_set = false;
    if (!attr_set) {
        cudaFuncSetAttribute(mlp_kernel, cudaFuncAttributeMaxDynamicSharedMemorySize,
                             SMEM_MLP);
        cudaFuncSetAttribute(pcomp_kernel, cudaFuncAttributeMaxDynamicSharedMemorySize,
                             SMEM_PC);
        attr_set = true;
    }

    cudaMemsetAsync(d_out, 0, (size_t)out_size * sizeof(float));
    reset_kernel<<<1, 1>>>();
    prep_kernel<<<320, 256>>>(W1o, W1i, W2o, W2i);
    partition_kernel<<<(E + 255) / 256, 256>>>(ei, E);
    pcomp_kernel<<<dim3((N + 127) / 128, 2), NTH, SMEM_PC>>>(x, b1o, b1i, N);

    dim3 grid((E + TILE - 1) / TILE, 2);
    mlp_kernel<<<grid, NTH, SMEM_MLP>>>(ei, ea, b2o, b2i, E, out);
}